// round 2
// baseline (speedup 1.0000x reference)
#include <cuda_runtime.h>
#include <cuda_bf16.h>

// Problem constants
#define NN 200000
#define FF 602
#define DD 128
#define HH 256
#define CC 41
#define BB 1024
#define S1 25
#define S2 10

#define R1 (BB * S2)        // 10240 hop0 rows
#define R2 (R1 * S1)        // 256000 hop1 entries
#define H2 (2 * HH)         // 512

// ---------------- scratch (device globals; no allocation) ----------------
__device__ int   g_hop0[R1];
__device__ int   g_hop1[R2];
__device__ float g_fhop0[(size_t)R1 * FF];       // features[hop0]      [10240,602]
__device__ float g_neigh1[(size_t)R1 * FF];      // mean feats of hop1  [10240,602]
__device__ float g_fx[(size_t)BB * FF];          // features[x]         [1024,602]
__device__ float g_fhop0_mean[(size_t)BB * FF];  // mean over S2        [1024,602]
__device__ float g_featmap1[(size_t)R1 * H2];    // [10240,512]
__device__ float g_x1[(size_t)BB * H2];          // [1024,512]
__device__ float g_featmap0[(size_t)BB * H2];    // [1024,512]
__device__ float g_out2[(size_t)BB * H2];        // [1024,512]

// ---------------- index construction ----------------
__global__ void hop0_kernel(const int* __restrict__ x, const int* __restrict__ adj,
                            const int* __restrict__ perm0) {
    int i = blockIdx.x * blockDim.x + threadIdx.x;
    if (i < R1) {
        int b = i / S2, s = i % S2;
        g_hop0[i] = __ldg(&adj[(long)__ldg(&x[b]) * DD + __ldg(&perm0[s])]);
    }
}

__global__ void hop1_kernel(const int* __restrict__ adj, const int* __restrict__ perm1) {
    int i = blockIdx.x * blockDim.x + threadIdx.x;
    if (i < R2) {
        int r = i / S1, t = i % S1;
        g_hop1[i] = __ldg(&adj[(long)g_hop0[r] * DD + __ldg(&perm1[t])]);
    }
}

// ---------------- gathers ----------------
// One block per hop0 row: neigh1[r] = mean_t features[hop1[r,t]], fhop0[r] = features[hop0[r]]
__global__ void gather_kernel(const float* __restrict__ features) {
    int r = blockIdx.x;
    __shared__ int idx[S1 + 1];
    int t = threadIdx.x;
    if (t < S1) idx[t] = g_hop1[r * S1 + t];
    if (t == S1) idx[S1] = g_hop0[r];
    __syncthreads();

    const int F2 = FF / 2;  // 301 float2s (602 even; rows 8B-aligned)
    float2* out_n = (float2*)(g_neigh1 + (size_t)r * FF);
    float2* out_s = (float2*)(g_fhop0 + (size_t)r * FF);
    for (int j = t; j < F2; j += blockDim.x) {
        float ax = 0.f, ay = 0.f;
        #pragma unroll
        for (int u = 0; u < S1; u++) {
            float2 v = __ldg(&((const float2*)(features + (long)idx[u] * FF))[j]);
            ax += v.x; ay += v.y;
        }
        out_n[j] = make_float2(ax * (1.f / S1), ay * (1.f / S1));
        out_s[j] = __ldg(&((const float2*)(features + (long)idx[S1] * FF))[j]);
    }
}

// One block per seed: fx[b] = features[x[b]], fhop0_mean[b] = mean_s fhop0[b*S2+s]
__global__ void seed_kernel(const float* __restrict__ features, const int* __restrict__ x) {
    int b = blockIdx.x;
    long xi = __ldg(&x[b]);
    for (int j = threadIdx.x; j < FF; j += blockDim.x) {
        g_fx[(size_t)b * FF + j] = __ldg(&features[xi * FF + j]);
        float acc = 0.f;
        #pragma unroll
        for (int s = 0; s < S2; s++)
            acc += g_fhop0[((size_t)b * S2 + s) * FF + j];
        g_fhop0_mean[(size_t)b * FF + j] = acc * (1.f / S2);
    }
}

// x1[b] = mean over S2 of featmap1 rows
__global__ void reduce_x1_kernel() {
    int b = blockIdx.x;
    for (int j = threadIdx.x; j < H2; j += blockDim.x) {
        float acc = 0.f;
        #pragma unroll
        for (int s = 0; s < S2; s++)
            acc += g_featmap1[((size_t)b * S2 + s) * H2 + j];
        g_x1[(size_t)b * H2 + j] = acc * (1.f / S2);
    }
}

// ---------------- tiled fp32 GEMM: C[m, col_off+n] = act(A[m,:] . W[n,:] + bias[n]) ----------------
// A: [M,K] row-major, W: [N,K] row-major (computes A @ W^T)
template <int BM, int BN, int BK, int TM, int TN>
__global__ void sgemm_kernel(const float* __restrict__ A, const float* __restrict__ W,
                             const float* __restrict__ bias, float* __restrict__ C,
                             int M, int N, int K, int ldc, int col_off, int relu) {
    constexpr int TX = BN / TN;
    constexpr int TY = BM / TM;
    constexpr int NT = TX * TY;
    __shared__ float As[BK][BM + 4];
    __shared__ float Ws[BK][BN + 4];

    const int tid = threadIdx.x;
    const int tx = tid % TX;
    const int ty = tid / TX;
    const int bm = blockIdx.y * BM;
    const int bn = blockIdx.x * BN;

    const int ka = tid % BK;
    const int ra = tid / BK;
    constexpr int RSTEP = NT / BK;

    float acc[TM][TN];
    #pragma unroll
    for (int i = 0; i < TM; i++)
        #pragma unroll
        for (int j = 0; j < TN; j++) acc[i][j] = 0.f;

    for (int k0 = 0; k0 < K; k0 += BK) {
        bool kok = (k0 + ka) < K;
        #pragma unroll
        for (int r = ra; r < BM; r += RSTEP)
            As[ka][r] = kok ? A[(long)(bm + r) * K + k0 + ka] : 0.f;
        #pragma unroll
        for (int r = ra; r < BN; r += RSTEP)
            Ws[ka][r] = kok ? W[(long)(bn + r) * K + k0 + ka] : 0.f;
        __syncthreads();

        #pragma unroll
        for (int kk = 0; kk < BK; kk++) {
            float rA[TM], rW[TN];
            #pragma unroll
            for (int i = 0; i < TM; i++) rA[i] = As[kk][ty * TM + i];
            #pragma unroll
            for (int j = 0; j < TN; j++) rW[j] = Ws[kk][tx * TN + j];
            #pragma unroll
            for (int i = 0; i < TM; i++)
                #pragma unroll
                for (int j = 0; j < TN; j++)
                    acc[i][j] = fmaf(rA[i], rW[j], acc[i][j]);
        }
        __syncthreads();
    }

    #pragma unroll
    for (int i = 0; i < TM; i++) {
        int m = bm + ty * TM + i;
        #pragma unroll
        for (int j = 0; j < TN; j++) {
            int n = bn + tx * TN + j;
            float v = acc[i][j] + bias[n];
            if (relu) v = fmaxf(v, 0.f);
            C[(long)m * ldc + col_off + n] = v;
        }
    }
}

// ---------------- layernorm + classifier ----------------
__global__ void ln_cls_kernel(const float* __restrict__ ln_g, const float* __restrict__ ln_b,
                              const float* __restrict__ w_cls, const float* __restrict__ b_cls,
                              float* __restrict__ out) {
    int b = blockIdx.x;
    __shared__ float sh[H2];
    __shared__ float warp_s[8], warp_q[8];
    const float* row = g_out2 + (size_t)b * H2;
    int t = threadIdx.x;

    float v0 = row[t], v1 = row[t + 256];
    float s = v0 + v1, q = v0 * v0 + v1 * v1;
    #pragma unroll
    for (int o = 16; o; o >>= 1) {
        s += __shfl_down_sync(0xFFFFFFFFu, s, o);
        q += __shfl_down_sync(0xFFFFFFFFu, q, o);
    }
    int warp = t >> 5, lane = t & 31;
    if (lane == 0) { warp_s[warp] = s; warp_q[warp] = q; }
    __syncthreads();
    if (t == 0) {
        float S = 0.f, Q = 0.f;
        #pragma unroll
        for (int w = 0; w < 8; w++) { S += warp_s[w]; Q += warp_q[w]; }
        float mu = S / (float)H2;
        warp_s[0] = mu;
        warp_q[0] = rsqrtf(Q / (float)H2 - mu * mu + 1e-12f);
    }
    __syncthreads();
    float mu = warp_s[0], rstd = warp_q[0];
    sh[t]       = (v0 - mu) * rstd * ln_g[t]       + ln_b[t];
    sh[t + 256] = (v1 - mu) * rstd * ln_g[t + 256] + ln_b[t + 256];
    __syncthreads();

    for (int c = t; c < CC; c += blockDim.x) {
        float acc = b_cls[c];
        const float* wr = w_cls + (size_t)c * H2;
        #pragma unroll 8
        for (int k = 0; k < H2; k++) acc = fmaf(sh[k], wr[k], acc);
        out[(size_t)b * CC + c] = acc;
    }
}

// ---------------- launch ----------------
extern "C" void kernel_launch(void* const* d_in, const int* in_sizes, int n_in,
                              void* d_out, int out_size) {
    const int*   x         = (const int*)d_in[0];
    const int*   adj       = (const int*)d_in[1];
    const int*   perm0     = (const int*)d_in[2];
    const int*   perm1     = (const int*)d_in[3];
    const float* features  = (const float*)d_in[4];
    const float* w1a_self  = (const float*)d_in[5];
    const float* b1a_self  = (const float*)d_in[6];
    const float* w1a_neigh = (const float*)d_in[7];
    const float* b1a_neigh = (const float*)d_in[8];
    const float* w1b_self  = (const float*)d_in[9];
    const float* b1b_self  = (const float*)d_in[10];
    const float* w1b_neigh = (const float*)d_in[11];
    const float* b1b_neigh = (const float*)d_in[12];
    const float* w2_self   = (const float*)d_in[13];
    const float* b2_self   = (const float*)d_in[14];
    const float* w2_neigh  = (const float*)d_in[15];
    const float* b2_neigh  = (const float*)d_in[16];
    const float* ln_g      = (const float*)d_in[17];
    const float* ln_b      = (const float*)d_in[18];
    const float* w_cls     = (const float*)d_in[19];
    const float* b_cls     = (const float*)d_in[20];
    float* out = (float*)d_out;

    float* p_fhop0;      cudaGetSymbolAddress((void**)&p_fhop0, g_fhop0);
    float* p_neigh1;     cudaGetSymbolAddress((void**)&p_neigh1, g_neigh1);
    float* p_fx;         cudaGetSymbolAddress((void**)&p_fx, g_fx);
    float* p_fhop0_mean; cudaGetSymbolAddress((void**)&p_fhop0_mean, g_fhop0_mean);
    float* p_featmap1;   cudaGetSymbolAddress((void**)&p_featmap1, g_featmap1);
    float* p_x1;         cudaGetSymbolAddress((void**)&p_x1, g_x1);
    float* p_featmap0;   cudaGetSymbolAddress((void**)&p_featmap0, g_featmap0);
    float* p_out2;       cudaGetSymbolAddress((void**)&p_out2, g_out2);

    hop0_kernel<<<(R1 + 255) / 256, 256>>>(x, adj, perm0);
    hop1_kernel<<<(R2 + 255) / 256, 256>>>(adj, perm1);
    gather_kernel<<<R1, 256>>>(features);
    seed_kernel<<<BB, 256>>>(features, x);

    // Stage-1 big GEMMs: [10240,602] x [602,256] -> relu -> featmap1 halves
    dim3 gBig(HH / 64, R1 / 128);
    sgemm_kernel<128, 64, 16, 8, 4><<<gBig, 256>>>(p_fhop0, w1b_self, b1b_self, p_featmap1,
                                                   R1, HH, FF, H2, 0, 1);
    sgemm_kernel<128, 64, 16, 8, 4><<<gBig, 256>>>(p_neigh1, w1b_neigh, b1b_neigh, p_featmap1,
                                                   R1, HH, FF, H2, HH, 1);
    reduce_x1_kernel<<<BB, 256>>>();

    // Stage-1 small GEMMs: featmap0 halves
    dim3 gSm(HH / 64, BB / 64);
    sgemm_kernel<64, 64, 16, 4, 4><<<gSm, 256>>>(p_fx, w1a_self, b1a_self, p_featmap0,
                                                 BB, HH, FF, H2, 0, 1);
    sgemm_kernel<64, 64, 16, 4, 4><<<gSm, 256>>>(p_fhop0_mean, w1a_neigh, b1a_neigh, p_featmap0,
                                                 BB, HH, FF, H2, HH, 1);

    // Stage-2 GEMMs: out2 halves (K=512, no relu)
    sgemm_kernel<64, 64, 16, 4, 4><<<gSm, 256>>>(p_featmap0, w2_self, b2_self, p_out2,
                                                 BB, HH, H2, H2, 0, 0);
    sgemm_kernel<64, 64, 16, 4, 4><<<gSm, 256>>>(p_x1, w2_neigh, b2_neigh, p_out2,
                                                 BB, HH, H2, H2, HH, 0);

    // LayerNorm + classifier
    ln_cls_kernel<<<BB, 256>>>(ln_g, ln_b, w_cls, b_cls, out);
}

// round 4
// speedup vs baseline: 2.9582x; 2.9582x over previous
#include <cuda_runtime.h>
#include <cuda_bf16.h>
#include <cstdint>

// Problem constants
#define NN 200000
#define FF 602
#define DD 128
#define HH 256
#define CC 41
#define BB 1024
#define S1 25
#define S2 10

#define R1 (BB * S2)        // 10240 hop0 rows
#define R2 (R1 * S1)        // 256000 hop1 entries
#define H2 (2 * HH)         // 512
#define KP1 608             // FF padded to mult of 32
#define KP2 512             // H2 (already mult of 32)

// ---------------- scratch (device globals; no allocation) ----------------
__device__ int g_hop0[R1];
__device__ int g_hop1[R2];

// bf16 split planes for GEMM A operands
__device__ __nv_bfloat16 g_fhop0_h[(size_t)R1 * KP1], g_fhop0_l[(size_t)R1 * KP1];
__device__ __nv_bfloat16 g_neigh1_h[(size_t)R1 * KP1], g_neigh1_l[(size_t)R1 * KP1];
__device__ __nv_bfloat16 g_fx_h[(size_t)BB * KP1],    g_fx_l[(size_t)BB * KP1];
__device__ __nv_bfloat16 g_fmean_h[(size_t)BB * KP1], g_fmean_l[(size_t)BB * KP1];
__device__ __nv_bfloat16 g_fm0_h[(size_t)BB * KP2],   g_fm0_l[(size_t)BB * KP2];   // featmap0
__device__ __nv_bfloat16 g_x1_h[(size_t)BB * KP2],    g_x1_l[(size_t)BB * KP2];

// bf16 split planes for weights
__device__ __nv_bfloat16 g_w1bs_h[HH * KP1], g_w1bs_l[HH * KP1];
__device__ __nv_bfloat16 g_w1bn_h[HH * KP1], g_w1bn_l[HH * KP1];
__device__ __nv_bfloat16 g_w1as_h[HH * KP1], g_w1as_l[HH * KP1];
__device__ __nv_bfloat16 g_w1an_h[HH * KP1], g_w1an_l[HH * KP1];
__device__ __nv_bfloat16 g_w2s_h[HH * KP2],  g_w2s_l[HH * KP2];
__device__ __nv_bfloat16 g_w2n_h[HH * KP2],  g_w2n_l[HH * KP2];

// fp32 intermediates
__device__ float g_featmap1[(size_t)R1 * H2];   // [10240,512]
__device__ float g_out2[(size_t)BB * H2];       // [1024,512]

__device__ __forceinline__ void split2(float v, __nv_bfloat16& h, __nv_bfloat16& l) {
    h = __float2bfloat16(v);
    l = __float2bfloat16(v - __bfloat162float(h));
}

// ---------------- index construction ----------------
__global__ void hop0_kernel(const int* __restrict__ x, const int* __restrict__ adj,
                            const int* __restrict__ perm0) {
    int i = blockIdx.x * blockDim.x + threadIdx.x;
    if (i < R1) {
        int b = i / S2, s = i % S2;
        g_hop0[i] = __ldg(&adj[(long)__ldg(&x[b]) * DD + __ldg(&perm0[s])]);
    }
}

__global__ void hop1_kernel(const int* __restrict__ adj, const int* __restrict__ perm1) {
    int i = blockIdx.x * blockDim.x + threadIdx.x;
    if (i < R2) {
        int r = i / S1, t = i % S1;
        g_hop1[i] = __ldg(&adj[(long)g_hop0[r] * DD + __ldg(&perm1[t])]);
    }
}

// ---------------- weight split: fp32 [N,K] -> bf16 hi/lo [N,KP] ----------------
__global__ void split_w_kernel(const float* __restrict__ w, __nv_bfloat16* __restrict__ hi,
                               __nv_bfloat16* __restrict__ lo, int N, int K, int KP) {
    int i = blockIdx.x * blockDim.x + threadIdx.x;
    if (i < N * KP) {
        int n = i / KP, k = i % KP;
        float v = (k < K) ? __ldg(&w[(size_t)n * K + k]) : 0.f;
        split2(v, hi[i], lo[i]);
    }
}

// ---------------- gathers ----------------
// One block per hop0 row: neigh1[r] = mean_t features[hop1[r,t]], fhop0[r] = features[hop0[r]]
__global__ void gather_kernel(const float* __restrict__ features) {
    int r = blockIdx.x;
    __shared__ int idx[S1 + 1];
    int t = threadIdx.x;
    if (t < S1) idx[t] = g_hop1[r * S1 + t];
    if (t == S1) idx[S1] = g_hop0[r];
    __syncthreads();

    const int F2 = FF / 2;      // 301 real float2s
    const int P2 = KP1 / 2;     // 304 padded
    __nv_bfloat162* oh_n = (__nv_bfloat162*)(g_neigh1_h + (size_t)r * KP1);
    __nv_bfloat162* ol_n = (__nv_bfloat162*)(g_neigh1_l + (size_t)r * KP1);
    __nv_bfloat162* oh_s = (__nv_bfloat162*)(g_fhop0_h + (size_t)r * KP1);
    __nv_bfloat162* ol_s = (__nv_bfloat162*)(g_fhop0_l + (size_t)r * KP1);
    for (int j = t; j < P2; j += blockDim.x) {
        float ax = 0.f, ay = 0.f, sx = 0.f, sy = 0.f;
        if (j < F2) {
            #pragma unroll
            for (int u = 0; u < S1; u++) {
                float2 v = __ldg(&((const float2*)(features + (long)idx[u] * FF))[j]);
                ax += v.x; ay += v.y;
            }
            ax *= (1.f / S1); ay *= (1.f / S1);
            float2 sv = __ldg(&((const float2*)(features + (long)idx[S1] * FF))[j]);
            sx = sv.x; sy = sv.y;
        }
        __nv_bfloat162 h2, l2;
        split2(ax, h2.x, l2.x); split2(ay, h2.y, l2.y);
        oh_n[j] = h2; ol_n[j] = l2;
        split2(sx, h2.x, l2.x); split2(sy, h2.y, l2.y);
        oh_s[j] = h2; ol_s[j] = l2;
    }
}

// One block per seed: fx[b] = features[x[b]], fmean[b] = mean_s fhop0[b*S2+s]
__global__ void seed_kernel(const float* __restrict__ features, const int* __restrict__ x) {
    int b = blockIdx.x;
    long xi = __ldg(&x[b]);
    for (int j = threadIdx.x; j < KP1; j += blockDim.x) {
        float fv = (j < FF) ? __ldg(&features[xi * FF + j]) : 0.f;
        split2(fv, g_fx_h[(size_t)b * KP1 + j], g_fx_l[(size_t)b * KP1 + j]);
        float acc = 0.f;
        #pragma unroll
        for (int s = 0; s < S2; s++) {
            size_t o = ((size_t)b * S2 + s) * KP1 + j;
            acc += __bfloat162float(g_fhop0_h[o]) + __bfloat162float(g_fhop0_l[o]);
        }
        split2(acc * (1.f / S2), g_fmean_h[(size_t)b * KP1 + j], g_fmean_l[(size_t)b * KP1 + j]);
    }
}

// x1[b] = mean over S2 of featmap1 rows -> bf16 split
__global__ void reduce_x1_kernel() {
    int b = blockIdx.x;
    for (int j = threadIdx.x; j < H2; j += blockDim.x) {
        float acc = 0.f;
        #pragma unroll
        for (int s = 0; s < S2; s++)
            acc += g_featmap1[((size_t)b * S2 + s) * H2 + j];
        split2(acc * (1.f / S2), g_x1_h[(size_t)b * KP2 + j], g_x1_l[(size_t)b * KP2 + j]);
    }
}

// ---------------- tensor-core GEMM with split-bf16 (3-MMA) ----------------
// C[m, col_off + n] = act(A[m,:] . W[n,:] + bias[n]);  A ~ Ahi+Alo, W ~ Whi+Wlo
// MODE 0: fp32 out, no relu.  MODE 1: fp32 out, relu.  MODE 2: bf16 hi/lo out, relu.
__device__ __forceinline__ void mma16816(float* d, const uint32_t* a, const uint32_t* b) {
    asm volatile(
        "mma.sync.aligned.m16n8k16.row.col.f32.bf16.bf16.f32 "
        "{%0,%1,%2,%3}, {%4,%5,%6,%7}, {%8,%9}, {%0,%1,%2,%3};"
        : "+f"(d[0]), "+f"(d[1]), "+f"(d[2]), "+f"(d[3])
        : "r"(a[0]), "r"(a[1]), "r"(a[2]), "r"(a[3]), "r"(b[0]), "r"(b[1]));
}

template <int BM, int BN, int WM, int WN, int MODE>
__global__ void __launch_bounds__(WM * WN * 32)
mma_gemm(const __nv_bfloat16* __restrict__ Ahi, const __nv_bfloat16* __restrict__ Alo,
         const __nv_bfloat16* __restrict__ Whi, const __nv_bfloat16* __restrict__ Wlo,
         const float* __restrict__ bias,
         float* __restrict__ Cf, __nv_bfloat16* __restrict__ Chi, __nv_bfloat16* __restrict__ Clo,
         int KP, int ldc, int col_off) {
    constexpr int BK = 32;
    constexpr int KS = BK + 8;  // padded smem stride (bf16) -> conflict-free frag loads
    constexpr int THREADS = WM * WN * 32;
    constexpr int WTM = BM / WM, WTN = BN / WN;
    constexpr int MT = WTM / 16, NT = WTN / 8;

    __shared__ __nv_bfloat16 Ah[BM][KS], Al[BM][KS], Wh[BN][KS], Wl[BN][KS];

    const int tid = threadIdx.x;
    const int lane = tid & 31, warp = tid >> 5;
    const int wm = warp / WN, wn = warp % WN;
    const int bm = blockIdx.y * BM, bn = blockIdx.x * BN;

    float acc[MT][NT][4] = {};

    const int lrow = tid >> 2;
    const int lseg = (tid & 3) * 8;
    constexpr int ROWSTEP = THREADS / 4;

    for (int k0 = 0; k0 < KP; k0 += BK) {
        #pragma unroll
        for (int r = lrow; r < BM; r += ROWSTEP) {
            const size_t off = (size_t)(bm + r) * KP + k0 + lseg;
            *(uint4*)&Ah[r][lseg] = *(const uint4*)(Ahi + off);
            *(uint4*)&Al[r][lseg] = *(const uint4*)(Alo + off);
        }
        #pragma unroll
        for (int r = lrow; r < BN; r += ROWSTEP) {
            const size_t off = (size_t)(bn + r) * KP + k0 + lseg;
            *(uint4*)&Wh[r][lseg] = *(const uint4*)(Whi + off);
            *(uint4*)&Wl[r][lseg] = *(const uint4*)(Wlo + off);
        }
        __syncthreads();

        #pragma unroll
        for (int kk = 0; kk < 2; kk++) {
            const int kb = kk * 16 + (lane & 3) * 2;
            uint32_t afh[MT][4], afl[MT][4], bfh[NT][2], bfl[NT][2];
            #pragma unroll
            for (int mi = 0; mi < MT; mi++) {
                int r0 = wm * WTM + mi * 16 + (lane >> 2);
                afh[mi][0] = *(const uint32_t*)&Ah[r0][kb];
                afh[mi][1] = *(const uint32_t*)&Ah[r0 + 8][kb];
                afh[mi][2] = *(const uint32_t*)&Ah[r0][kb + 8];
                afh[mi][3] = *(const uint32_t*)&Ah[r0 + 8][kb + 8];
                afl[mi][0] = *(const uint32_t*)&Al[r0][kb];
                afl[mi][1] = *(const uint32_t*)&Al[r0 + 8][kb];
                afl[mi][2] = *(const uint32_t*)&Al[r0][kb + 8];
                afl[mi][3] = *(const uint32_t*)&Al[r0 + 8][kb + 8];
            }
            #pragma unroll
            for (int ni = 0; ni < NT; ni++) {
                int n0 = wn * WTN + ni * 8 + (lane >> 2);
                bfh[ni][0] = *(const uint32_t*)&Wh[n0][kb];
                bfh[ni][1] = *(const uint32_t*)&Wh[n0][kb + 8];
                bfl[ni][0] = *(const uint32_t*)&Wl[n0][kb];
                bfl[ni][1] = *(const uint32_t*)&Wl[n0][kb + 8];
            }
            #pragma unroll
            for (int mi = 0; mi < MT; mi++)
                #pragma unroll
                for (int ni = 0; ni < NT; ni++) {
                    mma16816(acc[mi][ni], afh[mi], bfh[ni]);
                    mma16816(acc[mi][ni], afh[mi], bfl[ni]);
                    mma16816(acc[mi][ni], afl[mi], bfh[ni]);
                }
        }
        __syncthreads();
    }

    // epilogue
    #pragma unroll
    for (int mi = 0; mi < MT; mi++) {
        #pragma unroll
        for (int ni = 0; ni < NT; ni++) {
            int r0 = bm + wm * WTM + mi * 16 + (lane >> 2);
            int cl = bn + wn * WTN + ni * 8 + (lane & 3) * 2;  // gemm-local n (even)
            float bz0 = __ldg(&bias[cl]), bz1 = __ldg(&bias[cl + 1]);
            #pragma unroll
            for (int h = 0; h < 2; h++) {
                int row = r0 + h * 8;
                float v0 = acc[mi][ni][2 * h] + bz0;
                float v1 = acc[mi][ni][2 * h + 1] + bz1;
                if (MODE >= 1) { v0 = fmaxf(v0, 0.f); v1 = fmaxf(v1, 0.f); }
                size_t o = (size_t)row * ldc + col_off + cl;
                if (MODE <= 1) {
                    *(float2*)(Cf + o) = make_float2(v0, v1);
                } else {
                    __nv_bfloat162 h2, l2;
                    split2(v0, h2.x, l2.x); split2(v1, h2.y, l2.y);
                    *(__nv_bfloat162*)(Chi + o) = h2;
                    *(__nv_bfloat162*)(Clo + o) = l2;
                }
            }
        }
    }
}

// ---------------- layernorm + classifier ----------------
__global__ void ln_cls_kernel(const float* __restrict__ ln_g, const float* __restrict__ ln_b,
                              const float* __restrict__ w_cls, const float* __restrict__ b_cls,
                              float* __restrict__ out) {
    int b = blockIdx.x;
    __shared__ float sh[H2];
    __shared__ float warp_s[8], warp_q[8];
    const float* row = g_out2 + (size_t)b * H2;
    int t = threadIdx.x;

    float v0 = row[t], v1 = row[t + 256];
    float s = v0 + v1, q = v0 * v0 + v1 * v1;
    #pragma unroll
    for (int o = 16; o; o >>= 1) {
        s += __shfl_down_sync(0xFFFFFFFFu, s, o);
        q += __shfl_down_sync(0xFFFFFFFFu, q, o);
    }
    int warp = t >> 5, lane = t & 31;
    if (lane == 0) { warp_s[warp] = s; warp_q[warp] = q; }
    __syncthreads();
    if (t == 0) {
        float S = 0.f, Q = 0.f;
        #pragma unroll
        for (int w = 0; w < 8; w++) { S += warp_s[w]; Q += warp_q[w]; }
        float mu = S / (float)H2;
        warp_s[0] = mu;
        warp_q[0] = rsqrtf(Q / (float)H2 - mu * mu + 1e-12f);
    }
    __syncthreads();
    float mu = warp_s[0], rstd = warp_q[0];
    sh[t]       = (v0 - mu) * rstd * ln_g[t]       + ln_b[t];
    sh[t + 256] = (v1 - mu) * rstd * ln_g[t + 256] + ln_b[t + 256];
    __syncthreads();

    for (int c = t; c < CC; c += blockDim.x) {
        float acc = b_cls[c];
        const float* wr = w_cls + (size_t)c * H2;
        #pragma unroll 8
        for (int k = 0; k < H2; k++) acc = fmaf(sh[k], wr[k], acc);
        out[(size_t)b * CC + c] = acc;
    }
}

// ---------------- launch ----------------
extern "C" void kernel_launch(void* const* d_in, const int* in_sizes, int n_in,
                              void* d_out, int out_size) {
    const int*   x         = (const int*)d_in[0];
    const int*   adj       = (const int*)d_in[1];
    const int*   perm0     = (const int*)d_in[2];
    const int*   perm1     = (const int*)d_in[3];
    const float* features  = (const float*)d_in[4];
    const float* w1a_self  = (const float*)d_in[5];
    const float* b1a_self  = (const float*)d_in[6];
    const float* w1a_neigh = (const float*)d_in[7];
    const float* b1a_neigh = (const float*)d_in[8];
    const float* w1b_self  = (const float*)d_in[9];
    const float* b1b_self  = (const float*)d_in[10];
    const float* w1b_neigh = (const float*)d_in[11];
    const float* b1b_neigh = (const float*)d_in[12];
    const float* w2_self   = (const float*)d_in[13];
    const float* b2_self   = (const float*)d_in[14];
    const float* w2_neigh  = (const float*)d_in[15];
    const float* b2_neigh  = (const float*)d_in[16];
    const float* ln_g      = (const float*)d_in[17];
    const float* ln_b      = (const float*)d_in[18];
    const float* w_cls     = (const float*)d_in[19];
    const float* b_cls     = (const float*)d_in[20];
    float* out = (float*)d_out;

    #define SYM(T, p, s) T* p; cudaGetSymbolAddress((void**)&p, s)
    SYM(__nv_bfloat16, p_fhop0_h, g_fhop0_h);  SYM(__nv_bfloat16, p_fhop0_l, g_fhop0_l);
    SYM(__nv_bfloat16, p_neigh1_h, g_neigh1_h); SYM(__nv_bfloat16, p_neigh1_l, g_neigh1_l);
    SYM(__nv_bfloat16, p_fx_h, g_fx_h);        SYM(__nv_bfloat16, p_fx_l, g_fx_l);
    SYM(__nv_bfloat16, p_fmean_h, g_fmean_h);  SYM(__nv_bfloat16, p_fmean_l, g_fmean_l);
    SYM(__nv_bfloat16, p_fm0_h, g_fm0_h);      SYM(__nv_bfloat16, p_fm0_l, g_fm0_l);
    SYM(__nv_bfloat16, p_x1_h, g_x1_h);        SYM(__nv_bfloat16, p_x1_l, g_x1_l);
    SYM(__nv_bfloat16, p_w1bs_h, g_w1bs_h);    SYM(__nv_bfloat16, p_w1bs_l, g_w1bs_l);
    SYM(__nv_bfloat16, p_w1bn_h, g_w1bn_h);    SYM(__nv_bfloat16, p_w1bn_l, g_w1bn_l);
    SYM(__nv_bfloat16, p_w1as_h, g_w1as_h);    SYM(__nv_bfloat16, p_w1as_l, g_w1as_l);
    SYM(__nv_bfloat16, p_w1an_h, g_w1an_h);    SYM(__nv_bfloat16, p_w1an_l, g_w1an_l);
    SYM(__nv_bfloat16, p_w2s_h, g_w2s_h);      SYM(__nv_bfloat16, p_w2s_l, g_w2s_l);
    SYM(__nv_bfloat16, p_w2n_h, g_w2n_h);      SYM(__nv_bfloat16, p_w2n_l, g_w2n_l);
    SYM(float, p_featmap1, g_featmap1);
    #undef SYM

    // indices + weight splits (independent of gathers)
    hop0_kernel<<<(R1 + 255) / 256, 256>>>(x, adj, perm0);
    hop1_kernel<<<(R2 + 255) / 256, 256>>>(adj, perm1);

    const int WT = 256;
    split_w_kernel<<<(HH * KP1 + WT - 1) / WT, WT>>>(w1b_self,  p_w1bs_h, p_w1bs_l, HH, FF, KP1);
    split_w_kernel<<<(HH * KP1 + WT - 1) / WT, WT>>>(w1b_neigh, p_w1bn_h, p_w1bn_l, HH, FF, KP1);
    split_w_kernel<<<(HH * KP1 + WT - 1) / WT, WT>>>(w1a_self,  p_w1as_h, p_w1as_l, HH, FF, KP1);
    split_w_kernel<<<(HH * KP1 + WT - 1) / WT, WT>>>(w1a_neigh, p_w1an_h, p_w1an_l, HH, FF, KP1);
    split_w_kernel<<<(HH * KP2 + WT - 1) / WT, WT>>>(w2_self,   p_w2s_h,  p_w2s_l,  HH, H2, KP2);
    split_w_kernel<<<(HH * KP2 + WT - 1) / WT, WT>>>(w2_neigh,  p_w2n_h,  p_w2n_l,  HH, H2, KP2);

    gather_kernel<<<R1, 256>>>(features);
    seed_kernel<<<BB, 256>>>(features, x);

    // Stage-1 big GEMMs: [10240,608] x [608,256] -> relu -> featmap1 fp32 halves
    {
        dim3 g(HH / 128, R1 / 128);
        mma_gemm<128, 128, 4, 2, 1><<<g, 256>>>(p_fhop0_h, p_fhop0_l, p_w1bs_h, p_w1bs_l,
                                                b1b_self, p_featmap1, nullptr, nullptr,
                                                KP1, H2, 0);
        mma_gemm<128, 128, 4, 2, 1><<<g, 256>>>(p_neigh1_h, p_neigh1_l, p_w1bn_h, p_w1bn_l,
                                                b1b_neigh, p_featmap1, nullptr, nullptr,
                                                KP1, H2, HH);
    }
    reduce_x1_kernel<<<BB, 256>>>();

    // Stage-1 small GEMMs -> featmap0 bf16 hi/lo halves (relu)
    {
        dim3 g(HH / 64, BB / 64);
        mma_gemm<64, 64, 2, 2, 2><<<g, 128>>>(p_fx_h, p_fx_l, p_w1as_h, p_w1as_l,
                                              b1a_self, nullptr, p_fm0_h, p_fm0_l,
                                              KP1, KP2, 0);
        mma_gemm<64, 64, 2, 2, 2><<<g, 128>>>(p_fmean_h, p_fmean_l, p_w1an_h, p_w1an_l,
                                              b1a_neigh, nullptr, p_fm0_h, p_fm0_l,
                                              KP1, KP2, HH);
    }

    // Stage-2 GEMMs -> out2 fp32 halves (no relu)
    {
        float* p_out2; cudaGetSymbolAddress((void**)&p_out2, g_out2);
        dim3 g(HH / 64, BB / 64);
        mma_gemm<64, 64, 2, 2, 0><<<g, 128>>>(p_fm0_h, p_fm0_l, p_w2s_h, p_w2s_l,
                                              b2_self, p_out2, nullptr, nullptr,
                                              KP2, H2, 0);
        mma_gemm<64, 64, 2, 2, 0><<<g, 128>>>(p_x1_h, p_x1_l, p_w2n_h, p_w2n_l,
                                              b2_neigh, p_out2, nullptr, nullptr,
                                              KP2, H2, HH);
    }

    // LayerNorm + classifier
    ln_cls_kernel<<<BB, 256>>>(ln_g, ln_b, w_cls, b_cls, out);
}

// round 5
// speedup vs baseline: 3.6977x; 1.2500x over previous
#include <cuda_runtime.h>
#include <cuda_bf16.h>
#include <cstdint>

// Problem constants
#define NN 200000
#define FF 602
#define DD 128
#define HH 256
#define CC 41
#define BB 1024
#define S1 25
#define S2 10

#define R1 (BB * S2)        // 10240 hop0 rows
#define R2 (R1 * S1)        // 256000 hop1 entries
#define H2 (2 * HH)         // 512
#define KP1 608             // FF padded to mult of 32
#define KP2 512             // H2 (already mult of 32)

// ---------------- scratch (device globals; no allocation) ----------------
__device__ int g_hop0[R1];
__device__ int g_hop1[R2];

__device__ __nv_bfloat16 g_fhop0_h[(size_t)R1 * KP1], g_fhop0_l[(size_t)R1 * KP1];
__device__ __nv_bfloat16 g_neigh1_h[(size_t)R1 * KP1], g_neigh1_l[(size_t)R1 * KP1];
__device__ __nv_bfloat16 g_fx_h[(size_t)BB * KP1],    g_fx_l[(size_t)BB * KP1];
__device__ __nv_bfloat16 g_fmean_h[(size_t)BB * KP1], g_fmean_l[(size_t)BB * KP1];
__device__ __nv_bfloat16 g_fm0_h[(size_t)BB * KP2],   g_fm0_l[(size_t)BB * KP2];
__device__ __nv_bfloat16 g_x1_h[(size_t)BB * KP2],    g_x1_l[(size_t)BB * KP2];

__device__ __nv_bfloat16 g_w1bs_h[HH * KP1], g_w1bs_l[HH * KP1];
__device__ __nv_bfloat16 g_w1bn_h[HH * KP1], g_w1bn_l[HH * KP1];
__device__ __nv_bfloat16 g_w1as_h[HH * KP1], g_w1as_l[HH * KP1];
__device__ __nv_bfloat16 g_w1an_h[HH * KP1], g_w1an_l[HH * KP1];
__device__ __nv_bfloat16 g_w2s_h[HH * KP2],  g_w2s_l[HH * KP2];
__device__ __nv_bfloat16 g_w2n_h[HH * KP2],  g_w2n_l[HH * KP2];

__device__ float g_featmap1[(size_t)R1 * H2];   // [10240,512]
__device__ float g_out2[(size_t)BB * H2];       // [1024,512]

__device__ __forceinline__ void split2(float v, __nv_bfloat16& h, __nv_bfloat16& l) {
    h = __float2bfloat16(v);
    l = __float2bfloat16(v - __bfloat162float(h));
}

__device__ __forceinline__ void cp16(void* s, const void* g) {
    uint32_t sa = (uint32_t)__cvta_generic_to_shared(s);
    asm volatile("cp.async.cg.shared.global [%0], [%1], 16;" :: "r"(sa), "l"(g));
}
#define CP_COMMIT() asm volatile("cp.async.commit_group;")
#define CP_WAIT1()  asm volatile("cp.async.wait_group 1;")
#define CP_WAIT0()  asm volatile("cp.async.wait_group 0;")

// ---------------- fused index construction ----------------
__global__ void hops_kernel(const int* __restrict__ x, const int* __restrict__ adj,
                            const int* __restrict__ perm0, const int* __restrict__ perm1) {
    int i = blockIdx.x * blockDim.x + threadIdx.x;
    if (i < R2) {
        int r = i / S1, t = i % S1;
        int b = r / S2, s = r % S2;
        int h0 = __ldg(&adj[(long)__ldg(&x[b]) * DD + __ldg(&perm0[s])]);
        g_hop1[i] = __ldg(&adj[(long)h0 * DD + __ldg(&perm1[t])]);
        if (t == 0) g_hop0[r] = h0;
    }
}

// ---------------- fused weight splits ----------------
__global__ void split_w4_kernel(const float* w0, const float* w1, const float* w2, const float* w3,
                                __nv_bfloat16* h0, __nv_bfloat16* h1, __nv_bfloat16* h2, __nv_bfloat16* h3,
                                __nv_bfloat16* l0, __nv_bfloat16* l1, __nv_bfloat16* l2, __nv_bfloat16* l3) {
    const float* ws[4] = {w0, w1, w2, w3};
    __nv_bfloat16* hs[4] = {h0, h1, h2, h3};
    __nv_bfloat16* ls[4] = {l0, l1, l2, l3};
    int sec = blockIdx.y;
    int i = blockIdx.x * blockDim.x + threadIdx.x;
    if (i < HH * KP1) {
        int n = i / KP1, k = i % KP1;
        float v = (k < FF) ? __ldg(&ws[sec][(size_t)n * FF + k]) : 0.f;
        split2(v, hs[sec][i], ls[sec][i]);
    }
}

__global__ void split_w2_kernel(const float* w0, const float* w1,
                                __nv_bfloat16* h0, __nv_bfloat16* h1,
                                __nv_bfloat16* l0, __nv_bfloat16* l1) {
    const float* ws[2] = {w0, w1};
    __nv_bfloat16* hs[2] = {h0, h1};
    __nv_bfloat16* ls[2] = {l0, l1};
    int sec = blockIdx.y;
    int i = blockIdx.x * blockDim.x + threadIdx.x;
    if (i < HH * KP2) {
        float v = __ldg(&ws[sec][i]);   // K == KP2, no padding
        split2(v, hs[sec][i], ls[sec][i]);
    }
}

// ---------------- gathers ----------------
__global__ void gather_kernel(const float* __restrict__ features) {
    int r = blockIdx.x;
    __shared__ int idx[S1 + 1];
    int t = threadIdx.x;
    if (t < S1) idx[t] = g_hop1[r * S1 + t];
    if (t == S1) idx[S1] = g_hop0[r];
    __syncthreads();

    const int F2 = FF / 2;      // 301 real float2s
    const int P2 = KP1 / 2;     // 304 padded
    __nv_bfloat162* oh_n = (__nv_bfloat162*)(g_neigh1_h + (size_t)r * KP1);
    __nv_bfloat162* ol_n = (__nv_bfloat162*)(g_neigh1_l + (size_t)r * KP1);
    __nv_bfloat162* oh_s = (__nv_bfloat162*)(g_fhop0_h + (size_t)r * KP1);
    __nv_bfloat162* ol_s = (__nv_bfloat162*)(g_fhop0_l + (size_t)r * KP1);
    for (int j = t; j < P2; j += blockDim.x) {
        float ax = 0.f, ay = 0.f, sx = 0.f, sy = 0.f;
        if (j < F2) {
            #pragma unroll
            for (int u = 0; u < S1; u++) {
                float2 v = __ldg(&((const float2*)(features + (long)idx[u] * FF))[j]);
                ax += v.x; ay += v.y;
            }
            ax *= (1.f / S1); ay *= (1.f / S1);
            float2 sv = __ldg(&((const float2*)(features + (long)idx[S1] * FF))[j]);
            sx = sv.x; sy = sv.y;
        }
        __nv_bfloat162 h2, l2;
        split2(ax, h2.x, l2.x); split2(ay, h2.y, l2.y);
        oh_n[j] = h2; ol_n[j] = l2;
        split2(sx, h2.x, l2.x); split2(sy, h2.y, l2.y);
        oh_s[j] = h2; ol_s[j] = l2;
    }
}

__global__ void seed_kernel(const float* __restrict__ features, const int* __restrict__ x) {
    int b = blockIdx.x;
    long xi = __ldg(&x[b]);
    for (int j = threadIdx.x; j < KP1; j += blockDim.x) {
        float fv = (j < FF) ? __ldg(&features[xi * FF + j]) : 0.f;
        split2(fv, g_fx_h[(size_t)b * KP1 + j], g_fx_l[(size_t)b * KP1 + j]);
        float acc = 0.f;
        #pragma unroll
        for (int s = 0; s < S2; s++) {
            size_t o = ((size_t)b * S2 + s) * KP1 + j;
            acc += __bfloat162float(g_fhop0_h[o]) + __bfloat162float(g_fhop0_l[o]);
        }
        split2(acc * (1.f / S2), g_fmean_h[(size_t)b * KP1 + j], g_fmean_l[(size_t)b * KP1 + j]);
    }
}

__global__ void reduce_x1_kernel() {
    int b = blockIdx.x;
    for (int j = threadIdx.x; j < H2; j += blockDim.x) {
        float acc = 0.f;
        #pragma unroll
        for (int s = 0; s < S2; s++)
            acc += g_featmap1[((size_t)b * S2 + s) * H2 + j];
        split2(acc * (1.f / S2), g_x1_h[(size_t)b * KP2 + j], g_x1_l[(size_t)b * KP2 + j]);
    }
}

// ---------------- cp.async double-buffered split-bf16 MMA GEMM ----------------
// MODE 0: fp32 out, no relu.  MODE 1: fp32 out, relu.  MODE 2: bf16 hi/lo out, relu.
__device__ __forceinline__ void mma16816(float* d, const uint32_t* a, const uint32_t* b) {
    asm volatile(
        "mma.sync.aligned.m16n8k16.row.col.f32.bf16.bf16.f32 "
        "{%0,%1,%2,%3}, {%4,%5,%6,%7}, {%8,%9}, {%0,%1,%2,%3};"
        : "+f"(d[0]), "+f"(d[1]), "+f"(d[2]), "+f"(d[3])
        : "r"(a[0]), "r"(a[1]), "r"(a[2]), "r"(a[3]), "r"(b[0]), "r"(b[1]));
}

template <int BM, int BN, int WM, int WN, int MODE>
__global__ void __launch_bounds__(WM * WN * 32)
mma_gemm(const __nv_bfloat16* __restrict__ Ahi, const __nv_bfloat16* __restrict__ Alo,
         const __nv_bfloat16* __restrict__ Whi, const __nv_bfloat16* __restrict__ Wlo,
         const float* __restrict__ bias,
         float* __restrict__ Cf, __nv_bfloat16* __restrict__ Chi, __nv_bfloat16* __restrict__ Clo,
         int KP, int ldc, int col_off) {
    constexpr int BK = 32;
    constexpr int KS = BK + 8;  // padded stride: frag b32 loads hit 32 distinct banks
    constexpr int THREADS = WM * WN * 32;
    constexpr int WTM = BM / WM, WTN = BN / WN;
    constexpr int MT = WTM / 16, NT = WTN / 8;
    constexpr int APLANE = BM * KS, WPLANE = BN * KS;
    constexpr int STAGE = 2 * APLANE + 2 * WPLANE;

    extern __shared__ __align__(16) __nv_bfloat16 dsm[];

    const int tid = threadIdx.x;
    const int lane = tid & 31, warp = tid >> 5;
    const int wm = warp / WN, wn = warp % WN;
    const int bm = blockIdx.y * BM, bn = blockIdx.x * BN;

    const int lrow = tid >> 2;
    const int lseg = (tid & 3) * 8;          // 16B chunk within BK row
    constexpr int ROWSTEP = THREADS / 4;

    float acc[MT][NT][4] = {};

    auto copy_tile = [&](int s, int k0) {
        __nv_bfloat16* Ah = dsm + s * STAGE;
        __nv_bfloat16* Al = Ah + APLANE;
        __nv_bfloat16* Wh = Al + APLANE;
        __nv_bfloat16* Wl = Wh + WPLANE;
        #pragma unroll
        for (int r = lrow; r < BM; r += ROWSTEP) {
            const size_t off = (size_t)(bm + r) * KP + k0 + lseg;
            cp16(Ah + r * KS + lseg, Ahi + off);
            cp16(Al + r * KS + lseg, Alo + off);
        }
        #pragma unroll
        for (int r = lrow; r < BN; r += ROWSTEP) {
            const size_t off = (size_t)(bn + r) * KP + k0 + lseg;
            cp16(Wh + r * KS + lseg, Whi + off);
            cp16(Wl + r * KS + lseg, Wlo + off);
        }
    };

    const int KT = KP / BK;
    copy_tile(0, 0);
    CP_COMMIT();

    for (int kt = 0; kt < KT; kt++) {
        const int cur = kt & 1;
        if (kt + 1 < KT) {
            copy_tile(cur ^ 1, (kt + 1) * BK);
            CP_COMMIT();
            CP_WAIT1();
        } else {
            CP_WAIT0();
        }
        __syncthreads();

        const __nv_bfloat16* Ah = dsm + cur * STAGE;
        const __nv_bfloat16* Al = Ah + APLANE;
        const __nv_bfloat16* Wh = Al + APLANE;
        const __nv_bfloat16* Wl = Wh + WPLANE;

        #pragma unroll
        for (int kk = 0; kk < 2; kk++) {
            const int kb = kk * 16 + (lane & 3) * 2;
            uint32_t afh[MT][4], afl[MT][4], bfh[NT][2], bfl[NT][2];
            #pragma unroll
            for (int mi = 0; mi < MT; mi++) {
                int r0 = wm * WTM + mi * 16 + (lane >> 2);
                afh[mi][0] = *(const uint32_t*)&Ah[r0 * KS + kb];
                afh[mi][1] = *(const uint32_t*)&Ah[(r0 + 8) * KS + kb];
                afh[mi][2] = *(const uint32_t*)&Ah[r0 * KS + kb + 8];
                afh[mi][3] = *(const uint32_t*)&Ah[(r0 + 8) * KS + kb + 8];
                afl[mi][0] = *(const uint32_t*)&Al[r0 * KS + kb];
                afl[mi][1] = *(const uint32_t*)&Al[(r0 + 8) * KS + kb];
                afl[mi][2] = *(const uint32_t*)&Al[r0 * KS + kb + 8];
                afl[mi][3] = *(const uint32_t*)&Al[(r0 + 8) * KS + kb + 8];
            }
            #pragma unroll
            for (int ni = 0; ni < NT; ni++) {
                int n0 = wn * WTN + ni * 8 + (lane >> 2);
                bfh[ni][0] = *(const uint32_t*)&Wh[n0 * KS + kb];
                bfh[ni][1] = *(const uint32_t*)&Wh[n0 * KS + kb + 8];
                bfl[ni][0] = *(const uint32_t*)&Wl[n0 * KS + kb];
                bfl[ni][1] = *(const uint32_t*)&Wl[n0 * KS + kb + 8];
            }
            #pragma unroll
            for (int mi = 0; mi < MT; mi++)
                #pragma unroll
                for (int ni = 0; ni < NT; ni++) {
                    mma16816(acc[mi][ni], afh[mi], bfh[ni]);
                    mma16816(acc[mi][ni], afh[mi], bfl[ni]);
                    mma16816(acc[mi][ni], afl[mi], bfh[ni]);
                }
        }
        __syncthreads();
    }

    // epilogue
    #pragma unroll
    for (int mi = 0; mi < MT; mi++) {
        #pragma unroll
        for (int ni = 0; ni < NT; ni++) {
            int r0 = bm + wm * WTM + mi * 16 + (lane >> 2);
            int cl = bn + wn * WTN + ni * 8 + (lane & 3) * 2;
            float bz0 = __ldg(&bias[cl]), bz1 = __ldg(&bias[cl + 1]);
            #pragma unroll
            for (int h = 0; h < 2; h++) {
                int row = r0 + h * 8;
                float v0 = acc[mi][ni][2 * h] + bz0;
                float v1 = acc[mi][ni][2 * h + 1] + bz1;
                if (MODE >= 1) { v0 = fmaxf(v0, 0.f); v1 = fmaxf(v1, 0.f); }
                size_t o = (size_t)row * ldc + col_off + cl;
                if (MODE <= 1) {
                    *(float2*)(Cf + o) = make_float2(v0, v1);
                } else {
                    __nv_bfloat162 h2, l2;
                    split2(v0, h2.x, l2.x); split2(v1, h2.y, l2.y);
                    *(__nv_bfloat162*)(Chi + o) = h2;
                    *(__nv_bfloat162*)(Clo + o) = l2;
                }
            }
        }
    }
}

// ---------------- layernorm + classifier ----------------
__global__ void ln_cls_kernel(const float* __restrict__ ln_g, const float* __restrict__ ln_b,
                              const float* __restrict__ w_cls, const float* __restrict__ b_cls,
                              float* __restrict__ out) {
    int b = blockIdx.x;
    __shared__ float sh[H2];
    __shared__ float warp_s[8], warp_q[8];
    const float* row = g_out2 + (size_t)b * H2;
    int t = threadIdx.x;

    float v0 = row[t], v1 = row[t + 256];
    float s = v0 + v1, q = v0 * v0 + v1 * v1;
    #pragma unroll
    for (int o = 16; o; o >>= 1) {
        s += __shfl_down_sync(0xFFFFFFFFu, s, o);
        q += __shfl_down_sync(0xFFFFFFFFu, q, o);
    }
    int warp = t >> 5, lane = t & 31;
    if (lane == 0) { warp_s[warp] = s; warp_q[warp] = q; }
    __syncthreads();
    if (t == 0) {
        float S = 0.f, Q = 0.f;
        #pragma unroll
        for (int w = 0; w < 8; w++) { S += warp_s[w]; Q += warp_q[w]; }
        float mu = S / (float)H2;
        warp_s[0] = mu;
        warp_q[0] = rsqrtf(Q / (float)H2 - mu * mu + 1e-12f);
    }
    __syncthreads();
    float mu = warp_s[0], rstd = warp_q[0];
    sh[t]       = (v0 - mu) * rstd * ln_g[t]       + ln_b[t];
    sh[t + 256] = (v1 - mu) * rstd * ln_g[t + 256] + ln_b[t + 256];
    __syncthreads();

    for (int c = t; c < CC; c += blockDim.x) {
        float acc = b_cls[c];
        const float* wr = w_cls + (size_t)c * H2;
        #pragma unroll 8
        for (int k = 0; k < H2; k++) acc = fmaf(sh[k], wr[k], acc);
        out[(size_t)b * CC + c] = acc;
    }
}

// ---------------- launch ----------------
extern "C" void kernel_launch(void* const* d_in, const int* in_sizes, int n_in,
                              void* d_out, int out_size) {
    const int*   x         = (const int*)d_in[0];
    const int*   adj       = (const int*)d_in[1];
    const int*   perm0     = (const int*)d_in[2];
    const int*   perm1     = (const int*)d_in[3];
    const float* features  = (const float*)d_in[4];
    const float* w1a_self  = (const float*)d_in[5];
    const float* b1a_self  = (const float*)d_in[6];
    const float* w1a_neigh = (const float*)d_in[7];
    const float* b1a_neigh = (const float*)d_in[8];
    const float* w1b_self  = (const float*)d_in[9];
    const float* b1b_self  = (const float*)d_in[10];
    const float* w1b_neigh = (const float*)d_in[11];
    const float* b1b_neigh = (const float*)d_in[12];
    const float* w2_self   = (const float*)d_in[13];
    const float* b2_self   = (const float*)d_in[14];
    const float* w2_neigh  = (const float*)d_in[15];
    const float* b2_neigh  = (const float*)d_in[16];
    const float* ln_g      = (const float*)d_in[17];
    const float* ln_b      = (const float*)d_in[18];
    const float* w_cls     = (const float*)d_in[19];
    const float* b_cls     = (const float*)d_in[20];
    float* out = (float*)d_out;

    #define SYM(T, p, s) T* p; cudaGetSymbolAddress((void**)&p, s)
    SYM(__nv_bfloat16, p_fhop0_h, g_fhop0_h);  SYM(__nv_bfloat16, p_fhop0_l, g_fhop0_l);
    SYM(__nv_bfloat16, p_neigh1_h, g_neigh1_h); SYM(__nv_bfloat16, p_neigh1_l, g_neigh1_l);
    SYM(__nv_bfloat16, p_fx_h, g_fx_h);        SYM(__nv_bfloat16, p_fx_l, g_fx_l);
    SYM(__nv_bfloat16, p_fmean_h, g_fmean_h);  SYM(__nv_bfloat16, p_fmean_l, g_fmean_l);
    SYM(__nv_bfloat16, p_fm0_h, g_fm0_h);      SYM(__nv_bfloat16, p_fm0_l, g_fm0_l);
    SYM(__nv_bfloat16, p_x1_h, g_x1_h);        SYM(__nv_bfloat16, p_x1_l, g_x1_l);
    SYM(__nv_bfloat16, p_w1bs_h, g_w1bs_h);    SYM(__nv_bfloat16, p_w1bs_l, g_w1bs_l);
    SYM(__nv_bfloat16, p_w1bn_h, g_w1bn_h);    SYM(__nv_bfloat16, p_w1bn_l, g_w1bn_l);
    SYM(__nv_bfloat16, p_w1as_h, g_w1as_h);    SYM(__nv_bfloat16, p_w1as_l, g_w1as_l);
    SYM(__nv_bfloat16, p_w1an_h, g_w1an_h);    SYM(__nv_bfloat16, p_w1an_l, g_w1an_l);
    SYM(__nv_bfloat16, p_w2s_h, g_w2s_h);      SYM(__nv_bfloat16, p_w2s_l, g_w2s_l);
    SYM(__nv_bfloat16, p_w2n_h, g_w2n_h);      SYM(__nv_bfloat16, p_w2n_l, g_w2n_l);
    SYM(float, p_featmap1, g_featmap1);
    SYM(float, p_out2, g_out2);
    #undef SYM

    // big-GEMM instantiation needs >48KB dynamic smem
    constexpr int BIG_SMEM = 2 * (2 * 128 * 40 + 2 * 64 * 40) * (int)sizeof(__nv_bfloat16);  // 61440
    constexpr int SM_SMEM  = 2 * (2 * 64 * 40 + 2 * 64 * 40) * (int)sizeof(__nv_bfloat16);   // 40960
    static bool attr_done = false;
    if (!attr_done) {
        cudaFuncSetAttribute((const void*)mma_gemm<128, 64, 4, 1, 1>,
                             cudaFuncAttributeMaxDynamicSharedMemorySize, BIG_SMEM);
        attr_done = true;
    }

    // indices (fused hop0+hop1)
    hops_kernel<<<(R2 + 255) / 256, 256>>>(x, adj, perm0, perm1);

    // weight splits (fused: 2 launches)
    split_w4_kernel<<<dim3((HH * KP1 + 255) / 256, 4), 256>>>(
        w1b_self, w1b_neigh, w1a_self, w1a_neigh,
        p_w1bs_h, p_w1bn_h, p_w1as_h, p_w1an_h,
        p_w1bs_l, p_w1bn_l, p_w1as_l, p_w1an_l);
    split_w2_kernel<<<dim3((HH * KP2 + 255) / 256, 2), 256>>>(
        w2_self, w2_neigh, p_w2s_h, p_w2n_h, p_w2s_l, p_w2n_l);

    gather_kernel<<<R1, 256>>>(features);
    seed_kernel<<<BB, 256>>>(features, x);

    // Stage-1 big GEMMs: [10240,608] x [608,256] -> relu -> featmap1 fp32 halves
    {
        dim3 g(HH / 64, R1 / 128);   // (4, 80) = 320 blocks, 3/SM -> single wave
        mma_gemm<128, 64, 4, 1, 1><<<g, 128, BIG_SMEM>>>(
            p_fhop0_h, p_fhop0_l, p_w1bs_h, p_w1bs_l,
            b1b_self, p_featmap1, nullptr, nullptr, KP1, H2, 0);
        mma_gemm<128, 64, 4, 1, 1><<<g, 128, BIG_SMEM>>>(
            p_neigh1_h, p_neigh1_l, p_w1bn_h, p_w1bn_l,
            b1b_neigh, p_featmap1, nullptr, nullptr, KP1, H2, HH);
    }
    reduce_x1_kernel<<<BB, 256>>>();

    // Stage-1 small GEMMs -> featmap0 bf16 hi/lo halves (relu)
    {
        dim3 g(HH / 64, BB / 64);
        mma_gemm<64, 64, 2, 2, 2><<<g, 128, SM_SMEM>>>(
            p_fx_h, p_fx_l, p_w1as_h, p_w1as_l,
            b1a_self, nullptr, p_fm0_h, p_fm0_l, KP1, KP2, 0);
        mma_gemm<64, 64, 2, 2, 2><<<g, 128, SM_SMEM>>>(
            p_fmean_h, p_fmean_l, p_w1an_h, p_w1an_l,
            b1a_neigh, nullptr, p_fm0_h, p_fm0_l, KP1, KP2, HH);
    }

    // Stage-2 GEMMs -> out2 fp32 halves (no relu)
    {
        dim3 g(HH / 64, BB / 64);
        mma_gemm<64, 64, 2, 2, 0><<<g, 128, SM_SMEM>>>(
            p_fm0_h, p_fm0_l, p_w2s_h, p_w2s_l,
            b2_self, p_out2, nullptr, nullptr, KP2, H2, 0);
        mma_gemm<64, 64, 2, 2, 0><<<g, 128, SM_SMEM>>>(
            p_x1_h, p_x1_l, p_w2n_h, p_w2n_l,
            b2_neigh, p_out2, nullptr, nullptr, KP2, H2, HH);
    }

    // LayerNorm + classifier
    ln_cls_kernel<<<BB, 256>>>(ln_g, ln_b, w_cls, b_cls, out);
}